// round 3
// baseline (speedup 1.0000x reference)
#include <cuda_runtime.h>
#include <cuda_bf16.h>

// Segment-sum of weighted RGB over sorted ray indices.
// pred_rgb[r, c] = sum_{i : ray_indices[i]==r} weights[i] * rgb[i, c]
//
// Inputs (metadata order):
//   d_in[0] rgb_samples     float32 [N_SAMPLES, 3]
//   d_in[1] weights_samples float32 [N_SAMPLES, 1]
//   d_in[2] ray_indices     int32   [N_SAMPLES]   (sorted ascending)
//   d_in[3] n_rays          int32 scalar
// Output: float32 [N_RAYS, 3]

#define IPT 16  // samples per thread; rgb bytes per thread = 16*12 = 192 (16B-aligned)

__global__ void zero_out_kernel4(float4* __restrict__ out, int n4) {
    int i = blockIdx.x * blockDim.x + threadIdx.x;
    if (i < n4) out[i] = make_float4(0.f, 0.f, 0.f, 0.f);
}

__global__ void zero_out_tail(float* __restrict__ out, int start, int n) {
    int i = start + blockIdx.x * blockDim.x + threadIdx.x;
    if (i < n) out[i] = 0.0f;
}

__global__ __launch_bounds__(256) void integrate_kernel(
    const float4* __restrict__ rgb4,   // 3*N/4 float4
    const float4* __restrict__ w4,     // N/4 float4
    const int4*  __restrict__ idx4,    // N/4 int4
    float* __restrict__ out,
    int n_samples)
{
    int t = blockIdx.x * blockDim.x + threadIdx.x;
    long base = (long)t * IPT;
    if (base >= n_samples) return;

    // ---- vectorized loads: 4x int4 idx, 4x float4 weights, 12x float4 rgb ----
    // All independent -> 20 LDG.128 in flight per thread.
    int4 iv[4];
#pragma unroll
    for (int k = 0; k < 4; k++) iv[k] = idx4[t * 4 + k];
    float4 wv[4];
#pragma unroll
    for (int k = 0; k < 4; k++) wv[k] = w4[t * 4 + k];
    float4 r[12];
#pragma unroll
    for (int k = 0; k < 12; k++) r[k] = rgb4[t * 12 + k];

    const float* rf = reinterpret_cast<const float*>(r);
    const int*   idx = reinterpret_cast<const int*>(iv);
    const float* w   = reinterpret_cast<const float*>(wv);

    // ---- run-length accumulate over sorted indices, flush on change ----
    int cur = idx[0];
    float a0 = 0.f, a1 = 0.f, a2 = 0.f;
#pragma unroll
    for (int k = 0; k < IPT; k++) {
        int ik = idx[k];
        if (ik != cur) {
            atomicAdd(&out[3 * cur + 0], a0);
            atomicAdd(&out[3 * cur + 1], a1);
            atomicAdd(&out[3 * cur + 2], a2);
            cur = ik;
            a0 = a1 = a2 = 0.f;
        }
        a0 = fmaf(w[k], rf[3 * k + 0], a0);
        a1 = fmaf(w[k], rf[3 * k + 1], a1);
        a2 = fmaf(w[k], rf[3 * k + 2], a2);
    }
    atomicAdd(&out[3 * cur + 0], a0);
    atomicAdd(&out[3 * cur + 1], a1);
    atomicAdd(&out[3 * cur + 2], a2);
}

extern "C" void kernel_launch(void* const* d_in, const int* in_sizes, int n_in,
                              void* d_out, int out_size) {
    const float* rgb = (const float*)d_in[0];
    const float* wts = (const float*)d_in[1];
    const int*   idx = (const int*)d_in[2];
    float* out = (float*)d_out;

    int n_samples = in_sizes[2];          // element count of ray_indices

    // zero-init output (poisoned by harness; empty rays must be 0)
    {
        int n4 = out_size / 4;
        int threads = 256;
        int blocks = (n4 + threads - 1) / threads;
        if (blocks > 0)
            zero_out_kernel4<<<blocks, threads>>>((float4*)out, n4);
        int tail = out_size - n4 * 4;
        if (tail > 0)
            zero_out_tail<<<1, 32>>>(out, n4 * 4, out_size);
    }

    // main segment-sum
    {
        int total_threads = (n_samples + IPT - 1) / IPT;
        int threads = 256;
        int blocks = (total_threads + threads - 1) / threads;
        integrate_kernel<<<blocks, threads>>>(
            (const float4*)rgb, (const float4*)wts, (const int4*)idx,
            out, n_samples);
    }
}

// round 4
// speedup vs baseline: 1.0933x; 1.0933x over previous
#include <cuda_runtime.h>
#include <cuda_bf16.h>

// Segment-sum of weighted RGB over sorted ray indices.
// pred_rgb[r, c] = sum_{i : ray_indices[i]==r} weights[i] * rgb[i, c]
//
// Strategy: per-thread run-length accumulation over 8 consecutive samples
// (sorted indices -> ~1 atomic flush per thread), with rgb staged through
// shared memory so that ALL global loads are fully coalesced:
//   - rgb: 24 coalesced scalar LDG.32 per thread, smem layout padded
//     (addr = flat + flat/24, i.e. stride 25 per owner) -> conflict-free LDS.
//   - weights/idx: blocked vector loads (2x line amplification, acceptable).

#define IPT 8
#define BLOCK 256
#define SPB (BLOCK * IPT)          // 2048 samples per block
#define RGB_FLOATS (SPB * 3)       // 6144 floats per block
#define SM_RGB (BLOCK * 25)        // padded smem floats (25 per thread)

__global__ void zero_out_kernel4(float4* __restrict__ out, int n4) {
    int i = blockIdx.x * blockDim.x + threadIdx.x;
    if (i < n4) out[i] = make_float4(0.f, 0.f, 0.f, 0.f);
}

__global__ void zero_out_tail(float* __restrict__ out, int start, int n) {
    int i = start + blockIdx.x * blockDim.x + threadIdx.x;
    if (i < n) out[i] = 0.0f;
}

__global__ __launch_bounds__(BLOCK) void integrate_kernel(
    const float* __restrict__ rgbf,    // [N*3] floats
    const float* __restrict__ wf,      // [N] floats
    const int*   __restrict__ idxf,    // [N] ints
    float* __restrict__ out,
    int n_samples)
{
    __shared__ float srgb[SM_RGB];

    const int  tid  = threadIdx.x;
    const long base = (long)blockIdx.x * SPB;

    if (base + SPB <= n_samples) {
        // ---------- fast path: full tile ----------
        // per-thread blocked vector loads of idx / weights (issue early for MLP)
        const int4*   idx4 = (const int4*)(idxf) + (base >> 2);
        const float4* w4   = (const float4*)(wf) + (base >> 2);
        int4   i0 = idx4[tid * 2 + 0];
        int4   i1 = idx4[tid * 2 + 1];
        float4 w0 = w4[tid * 2 + 0];
        float4 w1 = w4[tid * 2 + 1];

        // coalesced rgb loads: 24 independent LDG.32 per thread
        const float* rbase = rgbf + base * 3;
        float v[24];
#pragma unroll
        for (int m = 0; m < 24; m++)
            v[m] = rbase[m * BLOCK + tid];

        // scatter into padded smem: flat -> flat + flat/24  (conflict-free on read)
#pragma unroll
        for (int m = 0; m < 24; m++) {
            int flat = m * BLOCK + tid;
            srgb[flat + flat / 24] = v[m];
        }
        __syncthreads();

        // gather this thread's 24 rgb floats (stride-25 base -> no bank conflicts)
        float rf[24];
#pragma unroll
        for (int m = 0; m < 24; m++)
            rf[m] = srgb[tid * 25 + m];

        int   idx[IPT] = {i0.x, i0.y, i0.z, i0.w, i1.x, i1.y, i1.z, i1.w};
        float w[IPT]   = {w0.x, w0.y, w0.z, w0.w, w1.x, w1.y, w1.z, w1.w};

        int cur = idx[0];
        float a0 = 0.f, a1 = 0.f, a2 = 0.f;
#pragma unroll
        for (int k = 0; k < IPT; k++) {
            int ik = idx[k];
            if (ik != cur) {
                atomicAdd(&out[3 * cur + 0], a0);
                atomicAdd(&out[3 * cur + 1], a1);
                atomicAdd(&out[3 * cur + 2], a2);
                cur = ik;
                a0 = a1 = a2 = 0.f;
            }
            a0 = fmaf(w[k], rf[3 * k + 0], a0);
            a1 = fmaf(w[k], rf[3 * k + 1], a1);
            a2 = fmaf(w[k], rf[3 * k + 2], a2);
        }
        atomicAdd(&out[3 * cur + 0], a0);
        atomicAdd(&out[3 * cur + 1], a1);
        atomicAdd(&out[3 * cur + 2], a2);
    } else {
        // ---------- tail path: per-sample guarded scalar ----------
        long s0 = base + (long)tid * IPT;
        if (s0 >= n_samples) return;
        int cur = idxf[s0];
        float a0 = 0.f, a1 = 0.f, a2 = 0.f;
        for (int k = 0; k < IPT; k++) {
            long s = s0 + k;
            if (s >= n_samples) break;
            int ik = idxf[s];
            if (ik != cur) {
                atomicAdd(&out[3 * cur + 0], a0);
                atomicAdd(&out[3 * cur + 1], a1);
                atomicAdd(&out[3 * cur + 2], a2);
                cur = ik;
                a0 = a1 = a2 = 0.f;
            }
            float wk = wf[s];
            a0 = fmaf(wk, rgbf[3 * s + 0], a0);
            a1 = fmaf(wk, rgbf[3 * s + 1], a1);
            a2 = fmaf(wk, rgbf[3 * s + 2], a2);
        }
        atomicAdd(&out[3 * cur + 0], a0);
        atomicAdd(&out[3 * cur + 1], a1);
        atomicAdd(&out[3 * cur + 2], a2);
    }
}

extern "C" void kernel_launch(void* const* d_in, const int* in_sizes, int n_in,
                              void* d_out, int out_size) {
    const float* rgb = (const float*)d_in[0];
    const float* wts = (const float*)d_in[1];
    const int*   idx = (const int*)d_in[2];
    float* out = (float*)d_out;

    int n_samples = in_sizes[2];

    // zero-init output (poisoned by harness; empty rays must be 0)
    {
        int n4 = out_size / 4;
        int threads = 256;
        int blocks = (n4 + threads - 1) / threads;
        if (blocks > 0)
            zero_out_kernel4<<<blocks, threads>>>((float4*)out, n4);
        if (out_size - n4 * 4 > 0)
            zero_out_tail<<<1, 32>>>(out, n4 * 4, out_size);
    }

    // main segment-sum
    {
        int blocks = (n_samples + SPB - 1) / SPB;
        integrate_kernel<<<blocks, BLOCK>>>(rgb, wts, idx, out, n_samples);
    }
}